// round 5
// baseline (speedup 1.0000x reference)
#include <cuda_runtime.h>
#include <cstdint>
#include <math.h>

#define SEQ   2048
#define DIM   512
#define NHEAD 8
#define HDIM  64
#define FFND  2048
#define NKEYS 128   // 64 local + 38 medium + 26 global

// ---------------- scratch (device globals; no allocation allowed) ----------
__device__ float g_xn [SEQ * DIM];
__device__ float g_qkv[SEQ * 3 * DIM];
__device__ float g_ctx[SEQ * DIM];
__device__ float g_x1 [SEQ * DIM];
__device__ float g_h  [SEQ * DIM];
__device__ float g_ffn[SEQ * FFND];

// ---------------- LayerNorm: one 128-thread block per row ------------------
__global__ void ln_kernel(const float* __restrict__ x,
                          const float* __restrict__ g,
                          const float* __restrict__ b,
                          float* __restrict__ o)
{
    int row = blockIdx.x;
    int t   = threadIdx.x;
    float4 v = ((const float4*)(x + row * DIM))[t];

    float s  = v.x + v.y + v.z + v.w;
    float ss = v.x*v.x + v.y*v.y + v.z*v.z + v.w*v.w;

    __shared__ float rs[4], rss[4];
    #pragma unroll
    for (int off = 16; off; off >>= 1) {
        s  += __shfl_xor_sync(0xffffffffu, s,  off);
        ss += __shfl_xor_sync(0xffffffffu, ss, off);
    }
    if ((t & 31) == 0) { rs[t >> 5] = s; rss[t >> 5] = ss; }
    __syncthreads();
    s  = rs[0]  + rs[1]  + rs[2]  + rs[3];
    ss = rss[0] + rss[1] + rss[2] + rss[3];

    float mu  = s * (1.0f / DIM);
    float var = ss * (1.0f / DIM) - mu * mu;
    float r   = rsqrtf(var + 1e-5f);

    float4 gv = ((const float4*)g)[t];
    float4 bv = ((const float4*)b)[t];
    float4 ov;
    ov.x = (v.x - mu) * r * gv.x + bv.x;
    ov.y = (v.y - mu) * r * gv.y + bv.y;
    ov.z = (v.z - mu) * r * gv.z + bv.z;
    ov.w = (v.w - mu) * r * gv.w + bv.w;
    ((float4*)(o + row * DIM))[t] = ov;
}

// ---------------- tf32 helpers ---------------------------------------------
__device__ __forceinline__ float tf32r(float x) {
    uint32_t u;
    asm("cvt.rna.tf32.f32 %0, %1;" : "=r"(u) : "f"(x));
    return __uint_as_float(u);
}

__device__ __forceinline__ void mma_tf32(float* c, const uint32_t* a, const uint32_t* b) {
    asm volatile(
        "mma.sync.aligned.m16n8k8.row.col.f32.tf32.tf32.f32 "
        "{%0,%1,%2,%3},{%4,%5,%6,%7},{%8,%9},{%0,%1,%2,%3};"
        : "+f"(c[0]), "+f"(c[1]), "+f"(c[2]), "+f"(c[3])
        : "r"(a[0]), "r"(a[1]), "r"(a[2]), "r"(a[3]), "r"(b[0]), "r"(b[1]));
}

// ---------------- 3xTF32 tensor-core GEMM ----------------------------------
// C = A[MxK] @ B[KxN] + bias (+res | gelu).  BK=16, 256 threads.
// A,B pre-split into (hi,lo) tf32 in smem; acc += Ah*Bh + Ah*Bl + Al*Bh.
// EPI: 0 bias, 1 bias+residual, 2 bias+gelu(exact)
template<int BM, int BN, int WARPS_M, int WARPS_N, int EPI>
__global__ void __launch_bounds__(256, (BN == 128) ? 1 : 2)
tc_gemm(const float* __restrict__ A, const float* __restrict__ B,
        const float* __restrict__ bias, const float* __restrict__ res,
        float* __restrict__ C, int N, int K)
{
    constexpr int WM  = BM / WARPS_M;
    constexpr int WN  = BN / WARPS_N;
    constexpr int MT  = WM / 16;
    constexpr int NT  = WN / 8;
    constexpr int AST = BM + 8;
    constexpr int BST = BN + 8;
    constexpr int NBQ = BN / 64;             // B float4 per thread per stage
    constexpr int NAQ = (BM == 128) ? 2 : 1; // A float4 per thread per stage

    extern __shared__ float sm[];
    float* AH = sm;
    float* AL = AH + 2 * 16 * AST;
    float* BH = AL + 2 * 16 * AST;
    float* BL = BH + 2 * 16 * BST;

    const int tid  = threadIdx.x;
    const int warp = tid >> 5;
    const int lane = tid & 31;
    const int wm   = warp / WARPS_N;
    const int wn   = warp % WARPS_N;
    const int gid  = lane >> 2;
    const int tig  = lane & 3;

    // staging assignment
    const int am  = (BM == 128) ? (tid >> 1) : (tid & 63);
    const int akq = (BM == 128) ? ((tid & 1) * 8) : ((tid >> 6) * 4);
    const int bk  = tid >> 4;
    const int bn0 = (tid & 15) * 4 * NBQ;

    const float* Ag = A + ((long)(blockIdx.y * BM + am)) * K + akq;
    const float* Bg = B + (long)bk * N + blockIdx.x * BN + bn0;

    float acc[MT][NT][4];
    #pragma unroll
    for (int i = 0; i < MT; i++)
        #pragma unroll
        for (int j = 0; j < NT; j++)
            #pragma unroll
            for (int r = 0; r < 4; r++) acc[i][j][r] = 0.f;

    float4 apre[NAQ], bpre[NBQ];

    auto commit = [&](int buf) {
        float* ah_ = AH + buf * (16 * AST);
        float* al_ = AL + buf * (16 * AST);
        #pragma unroll
        for (int q = 0; q < NAQ; q++) {
            float xv[4] = {apre[q].x, apre[q].y, apre[q].z, apre[q].w};
            #pragma unroll
            for (int j = 0; j < 4; j++) {
                float h = tf32r(xv[j]);
                float l = tf32r(xv[j] - h);
                ah_[(akq + q * 4 + j) * AST + am] = h;
                al_[(akq + q * 4 + j) * AST + am] = l;
            }
        }
        float* bh_ = BH + buf * (16 * BST);
        float* bl_ = BL + buf * (16 * BST);
        #pragma unroll
        for (int q = 0; q < NBQ; q++) {
            float4 v = bpre[q];
            float4 h4, l4;
            h4.x = tf32r(v.x); l4.x = tf32r(v.x - h4.x);
            h4.y = tf32r(v.y); l4.y = tf32r(v.y - h4.y);
            h4.z = tf32r(v.z); l4.z = tf32r(v.z - h4.z);
            h4.w = tf32r(v.w); l4.w = tf32r(v.w - h4.w);
            *(float4*)&bh_[bk * BST + bn0 + q * 4] = h4;
            *(float4*)&bl_[bk * BST + bn0 + q * 4] = l4;
        }
    };

    // prologue: stage kt=0
    #pragma unroll
    for (int q = 0; q < NAQ; q++) apre[q] = *(const float4*)(Ag + q * 4);
    #pragma unroll
    for (int q = 0; q < NBQ; q++) bpre[q] = *(const float4*)(Bg + q * 4);
    commit(0);
    __syncthreads();

    const int NKT = K / 16;
    for (int kt = 0; kt < NKT; kt++) {
        int buf = kt & 1;
        if (kt + 1 < NKT) {
            const float* Ap = Ag + (kt + 1) * 16;
            #pragma unroll
            for (int q = 0; q < NAQ; q++) apre[q] = *(const float4*)(Ap + q * 4);
            const float* Bp = Bg + (long)(kt + 1) * 16 * N;
            #pragma unroll
            for (int q = 0; q < NBQ; q++) bpre[q] = *(const float4*)(Bp + q * 4);
        }

        const float* ahp = AH + buf * (16 * AST);
        const float* alp = AL + buf * (16 * AST);
        const float* bhp = BH + buf * (16 * BST);
        const float* blp = BL + buf * (16 * BST);
        const int m0 = wm * WM;
        const int n0 = wn * WN;

        #pragma unroll
        for (int ks = 0; ks < 2; ks++) {
            const int k0 = ks * 8;
            uint32_t ah[MT][4], al[MT][4], bh[NT][2], bl[NT][2];
            #pragma unroll
            for (int mt = 0; mt < MT; mt++) {
                int m = m0 + mt * 16 + gid;
                ah[mt][0] = __float_as_uint(ahp[(k0 + tig    ) * AST + m    ]);
                ah[mt][1] = __float_as_uint(ahp[(k0 + tig    ) * AST + m + 8]);
                ah[mt][2] = __float_as_uint(ahp[(k0 + tig + 4) * AST + m    ]);
                ah[mt][3] = __float_as_uint(ahp[(k0 + tig + 4) * AST + m + 8]);
                al[mt][0] = __float_as_uint(alp[(k0 + tig    ) * AST + m    ]);
                al[mt][1] = __float_as_uint(alp[(k0 + tig    ) * AST + m + 8]);
                al[mt][2] = __float_as_uint(alp[(k0 + tig + 4) * AST + m    ]);
                al[mt][3] = __float_as_uint(alp[(k0 + tig + 4) * AST + m + 8]);
            }
            #pragma unroll
            for (int nt = 0; nt < NT; nt++) {
                int n = n0 + nt * 8 + gid;
                bh[nt][0] = __float_as_uint(bhp[(k0 + tig    ) * BST + n]);
                bh[nt][1] = __float_as_uint(bhp[(k0 + tig + 4) * BST + n]);
                bl[nt][0] = __float_as_uint(blp[(k0 + tig    ) * BST + n]);
                bl[nt][1] = __float_as_uint(blp[(k0 + tig + 4) * BST + n]);
            }
            #pragma unroll
            for (int mt = 0; mt < MT; mt++)
                #pragma unroll
                for (int nt = 0; nt < NT; nt++) mma_tf32(acc[mt][nt], ah[mt], bh[nt]);
            #pragma unroll
            for (int mt = 0; mt < MT; mt++)
                #pragma unroll
                for (int nt = 0; nt < NT; nt++) mma_tf32(acc[mt][nt], ah[mt], bl[nt]);
            #pragma unroll
            for (int mt = 0; mt < MT; mt++)
                #pragma unroll
                for (int nt = 0; nt < NT; nt++) mma_tf32(acc[mt][nt], al[mt], bh[nt]);
        }

        if (kt + 1 < NKT) commit(buf ^ 1);
        __syncthreads();
    }

    // ---------------- epilogue ----------------
    const int rb = blockIdx.y * BM + wm * WM;
    const int cb = blockIdx.x * BN + wn * WN;
    #pragma unroll
    for (int mt = 0; mt < MT; mt++) {
        #pragma unroll
        for (int nt = 0; nt < NT; nt++) {
            int r0 = rb + mt * 16 + gid;
            int c0 = cb + nt * 8 + tig * 2;
            float b0 = bias[c0], b1 = bias[c0 + 1];
            float v00 = acc[mt][nt][0] + b0;
            float v01 = acc[mt][nt][1] + b1;
            float v10 = acc[mt][nt][2] + b0;
            float v11 = acc[mt][nt][3] + b1;
            if (EPI == 1) {
                v00 += res[(long)r0 * N + c0];
                v01 += res[(long)r0 * N + c0 + 1];
                v10 += res[(long)(r0 + 8) * N + c0];
                v11 += res[(long)(r0 + 8) * N + c0 + 1];
            }
            if (EPI == 2) {
                v00 = 0.5f * v00 * (1.0f + erff(v00 * 0.70710678118654752f));
                v01 = 0.5f * v01 * (1.0f + erff(v01 * 0.70710678118654752f));
                v10 = 0.5f * v10 * (1.0f + erff(v10 * 0.70710678118654752f));
                v11 = 0.5f * v11 * (1.0f + erff(v11 * 0.70710678118654752f));
            }
            *(float2*)&C[(long)r0 * N + c0]       = make_float2(v00, v01);
            *(float2*)&C[(long)(r0 + 8) * N + c0] = make_float2(v10, v11);
        }
    }
}

// ---------------- sparse Cantor attention -----------------------------------
// One 256-thread block per query position s; warp w owns head w.
// After one staging barrier, warps run fully independently (shuffle softmax).
__global__ __launch_bounds__(256) void attn_kernel(const float* __restrict__ qkv,
                                                   float* __restrict__ ctx)
{
    const int s = blockIdx.x;
    const int t = threadIdx.x;
    const int h = t >> 5;
    const int l = t & 31;

    __shared__ int   ki[NKEYS];
    __shared__ float qs[512];          // all 8 heads' q
    __shared__ float ws[NHEAD][NKEYS]; // softmax weights per head

    if (t < NKEYS) {
        int key;
        if (t < 64)        key = s + t - 32;                          // local
        else if (t < 102)  key = s + (t - 83) * 64;                   // medium
        else               key = (int)(((long long)(t - 102) * (SEQ - 1)) / 25); // global
        ki[t] = min(max(key, 0), SEQ - 1);
    }
    ((float2*)qs)[t] = ((const float2*)(qkv + (long)s * (3 * DIM)))[t];
    __syncthreads();

    const float* qh    = qs + h * HDIM;
    const float* Kbase = qkv + DIM + h * HDIM;

    // ---- scores: each lane owns 4 keys ----
    float sc[4];
    #pragma unroll
    for (int g = 0; g < 4; g++) {
        int key = ki[g * 32 + l];
        const float4* kr = (const float4*)(Kbase + (long)key * (3 * DIM));
        float dot = 0.f;
        #pragma unroll
        for (int i = 0; i < 16; i++) {
            float4 kv = kr[i];
            dot += kv.x * qh[4*i] + kv.y * qh[4*i+1] + kv.z * qh[4*i+2] + kv.w * qh[4*i+3];
        }
        sc[g] = dot * 0.125f;
    }

    // ---- warp softmax over 128 values (4 per lane) ----
    float m = fmaxf(fmaxf(sc[0], sc[1]), fmaxf(sc[2], sc[3]));
    #pragma unroll
    for (int off = 16; off; off >>= 1) m = fmaxf(m, __shfl_xor_sync(0xffffffffu, m, off));
    float e[4], sum = 0.f;
    #pragma unroll
    for (int g = 0; g < 4; g++) { e[g] = __expf(sc[g] - m); sum += e[g]; }
    #pragma unroll
    for (int off = 16; off; off >>= 1) sum += __shfl_xor_sync(0xffffffffu, sum, off);
    float inv = __frcp_rn(sum);
    #pragma unroll
    for (int g = 0; g < 4; g++) ws[h][g * 32 + l] = e[g] * inv;
    __syncwarp();

    // ---- V accumulation: lane owns 2 dims; each iter is a coalesced 256B row read ----
    const float* Vbase = qkv + 2 * DIM + h * HDIM + 2 * l;
    float ax = 0.f, ay = 0.f;
    #pragma unroll 8
    for (int k = 0; k < NKEYS; k++) {
        float wv = ws[h][k];
        float2 v = *(const float2*)(Vbase + (long)ki[k] * (3 * DIM));
        ax = fmaf(wv, v.x, ax);
        ay = fmaf(wv, v.y, ay);
    }
    *(float2*)(ctx + (long)s * DIM + h * HDIM + 2 * l) = make_float2(ax, ay);
}

// ---------------- launch ----------------------------------------------------
extern "C" void kernel_launch(void* const* d_in, const int* in_sizes, int n_in,
                              void* d_out, int out_size)
{
    const float* x     = (const float*)d_in[0];
    const float* ln1_g = (const float*)d_in[2];
    const float* ln1_b = (const float*)d_in[3];
    const float* ln2_g = (const float*)d_in[4];
    const float* ln2_b = (const float*)d_in[5];
    const float* wqkv  = (const float*)d_in[6];
    const float* bqkv  = (const float*)d_in[7];
    const float* wo    = (const float*)d_in[8];
    const float* bo    = (const float*)d_in[9];
    const float* w1    = (const float*)d_in[10];
    const float* b1    = (const float*)d_in[11];
    const float* w2    = (const float*)d_in[12];
    const float* b2    = (const float*)d_in[13];
    float* out = (float*)d_out;

    float *xn, *qkv, *ctx, *x1, *h, *ffn;
    cudaGetSymbolAddress((void**)&xn,  g_xn);
    cudaGetSymbolAddress((void**)&qkv, g_qkv);
    cudaGetSymbolAddress((void**)&ctx, g_ctx);
    cudaGetSymbolAddress((void**)&x1,  g_x1);
    cudaGetSymbolAddress((void**)&h,   g_h);
    cudaGetSymbolAddress((void**)&ffn, g_ffn);

    // smem: 2 bufs * 16 rows * (AST + BST) floats * 2 (hi+lo) * 4B
    const int SM_BIG = (2 * 16 * (128 + 8) * 2 + 2 * 16 * (128 + 8) * 2) * 4; // 69632
    const int SM_NAR = (2 * 16 * ( 64 + 8) * 2 + 2 * 16 * ( 64 + 8) * 2) * 4; // 36864

    cudaFuncSetAttribute(tc_gemm<128,128,2,4,0>, cudaFuncAttributeMaxDynamicSharedMemorySize, SM_BIG);
    cudaFuncSetAttribute(tc_gemm<128,128,2,4,2>, cudaFuncAttributeMaxDynamicSharedMemorySize, SM_BIG);
    cudaFuncSetAttribute(tc_gemm< 64, 64,2,4,1>, cudaFuncAttributeMaxDynamicSharedMemorySize, SM_NAR);

    // 1) xn = LN1(x)
    ln_kernel<<<SEQ, 128>>>(x, ln1_g, ln1_b, xn);

    // 2) qkv = xn @ wqkv + bqkv   [2048 x 1536], K=512
    tc_gemm<128,128,2,4,0><<<dim3(3 * DIM / 128, SEQ / 128), 256, SM_BIG>>>(
        xn, wqkv, bqkv, nullptr, qkv, 3 * DIM, DIM);

    // 3) sparse attention (block per s, warp per head)
    attn_kernel<<<SEQ, 256>>>(qkv, ctx);

    // 4) x1 = ctx @ wo + bo + x   [2048 x 512], K=512  (64x64 tiles -> 256 blocks)
    tc_gemm<64,64,2,4,1><<<dim3(DIM / 64, SEQ / 64), 256, SM_NAR>>>(
        ctx, wo, bo, x, x1, DIM, DIM);

    // 5) h = LN2(x1)
    ln_kernel<<<SEQ, 128>>>(x1, ln2_g, ln2_b, h);

    // 6) ffn = gelu(h @ w1 + b1)  [2048 x 2048], K=512
    tc_gemm<128,128,2,4,2><<<dim3(FFND / 128, SEQ / 128), 256, SM_BIG>>>(
        h, w1, b1, nullptr, ffn, FFND, DIM);

    // 7) out = ffn @ w2 + b2 + x1 [2048 x 512], K=2048
    tc_gemm<64,64,2,4,1><<<dim3(DIM / 64, SEQ / 64), 256, SM_NAR>>>(
        ffn, w2, b2, x1, out, DIM, FFND);
}

// round 6
// speedup vs baseline: 1.2490x; 1.2490x over previous
#include <cuda_runtime.h>
#include <cstdint>
#include <math.h>

#define SEQ   2048
#define DIM   512
#define NHEAD 8
#define HDIM  64
#define FFND  2048
#define NKEYS 128   // 64 local + 38 medium + 26 global

// ---------------- scratch (device globals; no allocation allowed) ----------
__device__ float g_xn [SEQ * DIM];
__device__ float g_qkv[SEQ * 3 * DIM];
__device__ float g_ctx[SEQ * DIM];
__device__ float g_x1 [SEQ * DIM];
__device__ float g_h  [SEQ * DIM];
__device__ float g_ffn[SEQ * FFND];

// ---------------- LayerNorm: one 128-thread block per row ------------------
__global__ void ln_kernel(const float* __restrict__ x,
                          const float* __restrict__ g,
                          const float* __restrict__ b,
                          float* __restrict__ o)
{
    int row = blockIdx.x;
    int t   = threadIdx.x;
    float4 v = ((const float4*)(x + row * DIM))[t];

    float s  = v.x + v.y + v.z + v.w;
    float ss = v.x*v.x + v.y*v.y + v.z*v.z + v.w*v.w;

    __shared__ float rs[4], rss[4];
    #pragma unroll
    for (int off = 16; off; off >>= 1) {
        s  += __shfl_xor_sync(0xffffffffu, s,  off);
        ss += __shfl_xor_sync(0xffffffffu, ss, off);
    }
    if ((t & 31) == 0) { rs[t >> 5] = s; rss[t >> 5] = ss; }
    __syncthreads();
    s  = rs[0]  + rs[1]  + rs[2]  + rs[3];
    ss = rss[0] + rss[1] + rss[2] + rss[3];

    float mu  = s * (1.0f / DIM);
    float var = ss * (1.0f / DIM) - mu * mu;
    float r   = rsqrtf(var + 1e-5f);

    float4 gv = ((const float4*)g)[t];
    float4 bv = ((const float4*)b)[t];
    float4 ov;
    ov.x = (v.x - mu) * r * gv.x + bv.x;
    ov.y = (v.y - mu) * r * gv.y + bv.y;
    ov.z = (v.z - mu) * r * gv.z + bv.z;
    ov.w = (v.w - mu) * r * gv.w + bv.w;
    ((float4*)(o + row * DIM))[t] = ov;
}

// ---------------- tf32 helpers ---------------------------------------------
__device__ __forceinline__ float tf32r(float x) {
    uint32_t u;
    asm("cvt.rna.tf32.f32 %0, %1;" : "=r"(u) : "f"(x));
    return __uint_as_float(u);
}

__device__ __forceinline__ void mma_tf32(float* c, const uint32_t* a, const uint32_t* b) {
    asm volatile(
        "mma.sync.aligned.m16n8k8.row.col.f32.tf32.tf32.f32 "
        "{%0,%1,%2,%3},{%4,%5,%6,%7},{%8,%9},{%0,%1,%2,%3};"
        : "+f"(c[0]), "+f"(c[1]), "+f"(c[2]), "+f"(c[3])
        : "r"(a[0]), "r"(a[1]), "r"(a[2]), "r"(a[3]), "r"(b[0]), "r"(b[1]));
}

// ---------------- 3xTF32 tensor-core GEMM ----------------------------------
// C = A[MxK] @ B[KxN] + bias (+res | gelu).  BK=16, 256 threads.
// EPI: 0 bias, 1 bias+residual, 2 bias+gelu(exact)
template<int BM, int BN, int WARPS_M, int WARPS_N, int EPI>
__global__ void __launch_bounds__(256, (BN == 128) ? 1 : 2)
tc_gemm(const float* __restrict__ A, const float* __restrict__ B,
        const float* __restrict__ bias, const float* __restrict__ res,
        float* __restrict__ C, int N, int K)
{
    constexpr int WM  = BM / WARPS_M;
    constexpr int WN  = BN / WARPS_N;
    constexpr int MT  = WM / 16;
    constexpr int NT  = WN / 8;
    constexpr int AST = BM + 8;
    constexpr int BST = BN + 8;
    constexpr int NBQ = BN / 64;
    constexpr int NAQ = (BM == 128) ? 2 : 1;

    extern __shared__ float sm[];
    float* AH = sm;
    float* AL = AH + 2 * 16 * AST;
    float* BH = AL + 2 * 16 * AST;
    float* BL = BH + 2 * 16 * BST;

    const int tid  = threadIdx.x;
    const int warp = tid >> 5;
    const int lane = tid & 31;
    const int wm   = warp / WARPS_N;
    const int wn   = warp % WARPS_N;
    const int gid  = lane >> 2;
    const int tig  = lane & 3;

    const int am  = (BM == 128) ? (tid >> 1) : (tid & 63);
    const int akq = (BM == 128) ? ((tid & 1) * 8) : ((tid >> 6) * 4);
    const int bk  = tid >> 4;
    const int bn0 = (tid & 15) * 4 * NBQ;

    const float* Ag = A + ((long)(blockIdx.y * BM + am)) * K + akq;
    const float* Bg = B + (long)bk * N + blockIdx.x * BN + bn0;

    float acc[MT][NT][4];
    #pragma unroll
    for (int i = 0; i < MT; i++)
        #pragma unroll
        for (int j = 0; j < NT; j++)
            #pragma unroll
            for (int r = 0; r < 4; r++) acc[i][j][r] = 0.f;

    float4 apre[NAQ], bpre[NBQ];

    auto commit = [&](int buf) {
        float* ah_ = AH + buf * (16 * AST);
        float* al_ = AL + buf * (16 * AST);
        #pragma unroll
        for (int q = 0; q < NAQ; q++) {
            float xv[4] = {apre[q].x, apre[q].y, apre[q].z, apre[q].w};
            #pragma unroll
            for (int j = 0; j < 4; j++) {
                float h = tf32r(xv[j]);
                float l = tf32r(xv[j] - h);
                ah_[(akq + q * 4 + j) * AST + am] = h;
                al_[(akq + q * 4 + j) * AST + am] = l;
            }
        }
        float* bh_ = BH + buf * (16 * BST);
        float* bl_ = BL + buf * (16 * BST);
        #pragma unroll
        for (int q = 0; q < NBQ; q++) {
            float4 v = bpre[q];
            float4 h4, l4;
            h4.x = tf32r(v.x); l4.x = tf32r(v.x - h4.x);
            h4.y = tf32r(v.y); l4.y = tf32r(v.y - h4.y);
            h4.z = tf32r(v.z); l4.z = tf32r(v.z - h4.z);
            h4.w = tf32r(v.w); l4.w = tf32r(v.w - h4.w);
            *(float4*)&bh_[bk * BST + bn0 + q * 4] = h4;
            *(float4*)&bl_[bk * BST + bn0 + q * 4] = l4;
        }
    };

    #pragma unroll
    for (int q = 0; q < NAQ; q++) apre[q] = *(const float4*)(Ag + q * 4);
    #pragma unroll
    for (int q = 0; q < NBQ; q++) bpre[q] = *(const float4*)(Bg + q * 4);
    commit(0);
    __syncthreads();

    const int NKT = K / 16;
    for (int kt = 0; kt < NKT; kt++) {
        int buf = kt & 1;
        if (kt + 1 < NKT) {
            const float* Ap = Ag + (kt + 1) * 16;
            #pragma unroll
            for (int q = 0; q < NAQ; q++) apre[q] = *(const float4*)(Ap + q * 4);
            const float* Bp = Bg + (long)(kt + 1) * 16 * N;
            #pragma unroll
            for (int q = 0; q < NBQ; q++) bpre[q] = *(const float4*)(Bp + q * 4);
        }

        const float* ahp = AH + buf * (16 * AST);
        const float* alp = AL + buf * (16 * AST);
        const float* bhp = BH + buf * (16 * BST);
        const float* blp = BL + buf * (16 * BST);
        const int m0 = wm * WM;
        const int n0 = wn * WN;

        #pragma unroll
        for (int ks = 0; ks < 2; ks++) {
            const int k0 = ks * 8;
            uint32_t ah[MT][4], al[MT][4], bh[NT][2], bl[NT][2];
            #pragma unroll
            for (int mt = 0; mt < MT; mt++) {
                int m = m0 + mt * 16 + gid;
                ah[mt][0] = __float_as_uint(ahp[(k0 + tig    ) * AST + m    ]);
                ah[mt][1] = __float_as_uint(ahp[(k0 + tig    ) * AST + m + 8]);
                ah[mt][2] = __float_as_uint(ahp[(k0 + tig + 4) * AST + m    ]);
                ah[mt][3] = __float_as_uint(ahp[(k0 + tig + 4) * AST + m + 8]);
                al[mt][0] = __float_as_uint(alp[(k0 + tig    ) * AST + m    ]);
                al[mt][1] = __float_as_uint(alp[(k0 + tig    ) * AST + m + 8]);
                al[mt][2] = __float_as_uint(alp[(k0 + tig + 4) * AST + m    ]);
                al[mt][3] = __float_as_uint(alp[(k0 + tig + 4) * AST + m + 8]);
            }
            #pragma unroll
            for (int nt = 0; nt < NT; nt++) {
                int n = n0 + nt * 8 + gid;
                bh[nt][0] = __float_as_uint(bhp[(k0 + tig    ) * BST + n]);
                bh[nt][1] = __float_as_uint(bhp[(k0 + tig + 4) * BST + n]);
                bl[nt][0] = __float_as_uint(blp[(k0 + tig    ) * BST + n]);
                bl[nt][1] = __float_as_uint(blp[(k0 + tig + 4) * BST + n]);
            }
            #pragma unroll
            for (int mt = 0; mt < MT; mt++)
                #pragma unroll
                for (int nt = 0; nt < NT; nt++) mma_tf32(acc[mt][nt], ah[mt], bh[nt]);
            #pragma unroll
            for (int mt = 0; mt < MT; mt++)
                #pragma unroll
                for (int nt = 0; nt < NT; nt++) mma_tf32(acc[mt][nt], ah[mt], bl[nt]);
            #pragma unroll
            for (int mt = 0; mt < MT; mt++)
                #pragma unroll
                for (int nt = 0; nt < NT; nt++) mma_tf32(acc[mt][nt], al[mt], bh[nt]);
        }

        if (kt + 1 < NKT) commit(buf ^ 1);
        __syncthreads();
    }

    const int rb = blockIdx.y * BM + wm * WM;
    const int cb = blockIdx.x * BN + wn * WN;
    #pragma unroll
    for (int mt = 0; mt < MT; mt++) {
        #pragma unroll
        for (int nt = 0; nt < NT; nt++) {
            int r0 = rb + mt * 16 + gid;
            int c0 = cb + nt * 8 + tig * 2;
            float b0 = bias[c0], b1 = bias[c0 + 1];
            float v00 = acc[mt][nt][0] + b0;
            float v01 = acc[mt][nt][1] + b1;
            float v10 = acc[mt][nt][2] + b0;
            float v11 = acc[mt][nt][3] + b1;
            if (EPI == 1) {
                v00 += res[(long)r0 * N + c0];
                v01 += res[(long)r0 * N + c0 + 1];
                v10 += res[(long)(r0 + 8) * N + c0];
                v11 += res[(long)(r0 + 8) * N + c0 + 1];
            }
            if (EPI == 2) {
                v00 = 0.5f * v00 * (1.0f + erff(v00 * 0.70710678118654752f));
                v01 = 0.5f * v01 * (1.0f + erff(v01 * 0.70710678118654752f));
                v10 = 0.5f * v10 * (1.0f + erff(v10 * 0.70710678118654752f));
                v11 = 0.5f * v11 * (1.0f + erff(v11 * 0.70710678118654752f));
            }
            *(float2*)&C[(long)r0 * N + c0]       = make_float2(v00, v01);
            *(float2*)&C[(long)(r0 + 8) * N + c0] = make_float2(v10, v11);
        }
    }
}

// ---------------- sparse Cantor attention -----------------------------------
// One 256-thread block per query s; warp h owns head h.
// Score phase: 2 keys per LDG.128 — lanes 0-15 read the full 256B K-slice of
// key 2k, lanes 16-31 of key 2k+1 (coalesced, 4 lines/instr), dot with a
// loop-invariant q fragment, 4-step shuffle reduce over the 16-lane group.
__global__ __launch_bounds__(256) void attn_kernel(const float* __restrict__ qkv,
                                                   float* __restrict__ ctx)
{
    const int s = blockIdx.x;
    const int t = threadIdx.x;
    const int h = t >> 5;
    const int l = t & 31;

    __shared__ int   ki[NKEYS];
    __shared__ float qs[512];
    __shared__ float ws[NHEAD][NKEYS];

    if (t < NKEYS) {
        int key;
        if (t < 64)        key = s + t - 32;                          // local
        else if (t < 102)  key = s + (t - 83) * 64;                   // medium
        else               key = (int)(((long long)(t - 102) * (SEQ - 1)) / 25); // global
        ki[t] = min(max(key, 0), SEQ - 1);
    }
    ((float2*)qs)[t] = ((const float2*)(qkv + (long)s * (3 * DIM)))[t];
    __syncthreads();

    const int   half = l >> 4;   // which key of the pair
    const int   q4   = l & 15;   // which float4 of the 64-float slice
    const float* qh  = qs + h * HDIM;
    const float4 qv  = ((const float4*)qh)[q4];
    const float* Kbase = qkv + DIM + h * HDIM;

    // ---- scores: 2 keys per iteration, fully coalesced ----
    #pragma unroll 4
    for (int kp = 0; kp < NKEYS / 2; kp++) {
        int key = ki[2 * kp + half];
        float4 kv = ((const float4*)(Kbase + (long)key * (3 * DIM)))[q4];
        float p = kv.x * qv.x + kv.y * qv.y + kv.z * qv.z + kv.w * qv.w;
        p += __shfl_xor_sync(0xffffffffu, p, 8);
        p += __shfl_xor_sync(0xffffffffu, p, 4);
        p += __shfl_xor_sync(0xffffffffu, p, 2);
        p += __shfl_xor_sync(0xffffffffu, p, 1);
        if (q4 == 0) ws[h][2 * kp + half] = p * 0.125f;
    }
    __syncwarp();

    // ---- warp softmax over 128 scores (4 per lane) ----
    float sc[4];
    #pragma unroll
    for (int g = 0; g < 4; g++) sc[g] = ws[h][g * 32 + l];
    float m = fmaxf(fmaxf(sc[0], sc[1]), fmaxf(sc[2], sc[3]));
    #pragma unroll
    for (int off = 16; off; off >>= 1) m = fmaxf(m, __shfl_xor_sync(0xffffffffu, m, off));
    float e[4], sum = 0.f;
    #pragma unroll
    for (int g = 0; g < 4; g++) { e[g] = __expf(sc[g] - m); sum += e[g]; }
    #pragma unroll
    for (int off = 16; off; off >>= 1) sum += __shfl_xor_sync(0xffffffffu, sum, off);
    float inv = __frcp_rn(sum);
    #pragma unroll
    for (int g = 0; g < 4; g++) ws[h][g * 32 + l] = e[g] * inv;
    __syncwarp();

    // ---- V accumulation: lane owns 2 dims; coalesced 256B row read per iter ----
    const float* Vbase = qkv + 2 * DIM + h * HDIM + 2 * l;
    float ax = 0.f, ay = 0.f;
    #pragma unroll 16
    for (int k = 0; k < NKEYS; k++) {
        float wv = ws[h][k];
        float2 v = *(const float2*)(Vbase + (long)ki[k] * (3 * DIM));
        ax = fmaf(wv, v.x, ax);
        ay = fmaf(wv, v.y, ay);
    }
    *(float2*)(ctx + (long)s * DIM + h * HDIM + 2 * l) = make_float2(ax, ay);
}

// ---------------- launch ----------------------------------------------------
extern "C" void kernel_launch(void* const* d_in, const int* in_sizes, int n_in,
                              void* d_out, int out_size)
{
    const float* x     = (const float*)d_in[0];
    const float* ln1_g = (const float*)d_in[2];
    const float* ln1_b = (const float*)d_in[3];
    const float* ln2_g = (const float*)d_in[4];
    const float* ln2_b = (const float*)d_in[5];
    const float* wqkv  = (const float*)d_in[6];
    const float* bqkv  = (const float*)d_in[7];
    const float* wo    = (const float*)d_in[8];
    const float* bo    = (const float*)d_in[9];
    const float* w1    = (const float*)d_in[10];
    const float* b1    = (const float*)d_in[11];
    const float* w2    = (const float*)d_in[12];
    const float* b2    = (const float*)d_in[13];
    float* out = (float*)d_out;

    float *xn, *qkv, *ctx, *x1, *h, *ffn;
    cudaGetSymbolAddress((void**)&xn,  g_xn);
    cudaGetSymbolAddress((void**)&qkv, g_qkv);
    cudaGetSymbolAddress((void**)&ctx, g_ctx);
    cudaGetSymbolAddress((void**)&x1,  g_x1);
    cudaGetSymbolAddress((void**)&h,   g_h);
    cudaGetSymbolAddress((void**)&ffn, g_ffn);

    const int SM_BIG = (2 * 16 * (128 + 8) * 2 + 2 * 16 * (128 + 8) * 2) * 4; // 69632
    const int SM_NAR = (2 * 16 * (128 + 8) * 2 + 2 * 16 * ( 64 + 8) * 2) * 4; // 53248

    cudaFuncSetAttribute(tc_gemm<128,128,2,4,0>, cudaFuncAttributeMaxDynamicSharedMemorySize, SM_BIG);
    cudaFuncSetAttribute(tc_gemm<128,128,2,4,2>, cudaFuncAttributeMaxDynamicSharedMemorySize, SM_BIG);
    cudaFuncSetAttribute(tc_gemm<128, 64,4,2,1>, cudaFuncAttributeMaxDynamicSharedMemorySize, SM_NAR);

    // 1) xn = LN1(x)
    ln_kernel<<<SEQ, 128>>>(x, ln1_g, ln1_b, xn);

    // 2) qkv = xn @ wqkv + bqkv   [2048 x 1536], K=512
    tc_gemm<128,128,2,4,0><<<dim3(3 * DIM / 128, SEQ / 128), 256, SM_BIG>>>(
        xn, wqkv, bqkv, nullptr, qkv, 3 * DIM, DIM);

    // 3) sparse attention (block per s, warp per head, coalesced gather)
    attn_kernel<<<SEQ, 256>>>(qkv, ctx);

    // 4) x1 = ctx @ wo + bo + x   [2048 x 512], K=512
    tc_gemm<128,64,4,2,1><<<dim3(DIM / 64, SEQ / 128), 256, SM_NAR>>>(
        ctx, wo, bo, x, x1, DIM, DIM);

    // 5) h = LN2(x1)
    ln_kernel<<<SEQ, 128>>>(x1, ln2_g, ln2_b, h);

    // 6) ffn = gelu(h @ w1 + b1)  [2048 x 2048], K=512
    tc_gemm<128,128,2,4,2><<<dim3(FFND / 128, SEQ / 128), 256, SM_BIG>>>(
        h, w1, b1, nullptr, ffn, FFND, DIM);

    // 7) out = ffn @ w2 + b2 + x1 [2048 x 512], K=2048
    tc_gemm<128,64,4,2,1><<<dim3(DIM / 64, SEQ / 128), 256, SM_NAR>>>(
        ffn, w2, b2, x1, out, DIM, FFND);
}